// round 5
// baseline (speedup 1.0000x reference)
#include <cuda_runtime.h>
#include <cstdint>

#define KS    9
#define PADV  4
#define CIN   32
#define COUT  32
#define HH    192
#define WW    192
#define NB    16
#define CHW   (HH * WW)

#define TILE  64
#define SROW  72                 // 64 + 8 halo
#define TILE_ELEMS (SROW * SROW) // 5184 floats = 1296 16B chunks
#define NCHUNK 1296
#define WROW  10                 // 9 taps padded to 10 u64 (16B alignment)

typedef unsigned long long u64;

// Precomputed Gaussian kernels, duplicated as {w,w} u64 pairs, rows padded to 10.
__device__ u64 g_w2p[COUT * CIN * 9 * WROW];

// ---------------------------------------------------------------------------
// Phase 1: build normalized anisotropic Gaussian kernels from (sx, sy, theta)
// ---------------------------------------------------------------------------
__global__ void gk_compute(const float* __restrict__ wp) {
    int co = blockIdx.x;
    int ci = threadIdx.x;
    const float* p = wp + (co * CIN + ci) * 3;
    float sx = p[0], sy = p[1], th = p[2];
    float rad = th * 0.017453292519943295f;   // th / 180 * pi
    float c = cosf(rad), s = sinf(rad);
    float sx2 = sx * sx, sy2 = sy * sy;
    float a = c * c * sx2 + s * s * sy2;
    float b = c * s * (sx2 - sy2);
    float d = s * s * sx2 + c * c * sy2;
    float det = a * d - b * b;
    float ia = d / det, ib = -b / det, idd = a / det;

    float ker[81];
    float sum = 0.f;
    #pragma unroll
    for (int ky = 0; ky < 9; ky++) {
        float yy = (float)(ky - 4);
        #pragma unroll
        for (int kx = 0; kx < 9; kx++) {
            float xx = (float)(kx - 4);
            float q = ia * xx * xx + 2.0f * ib * xx * yy + idd * yy * yy;
            float v = expf(-0.5f * q);
            ker[ky * 9 + kx] = v;
            sum += v;
        }
    }
    float inv = 1.0f / sum;
    u64* dst = &g_w2p[(co * CIN + ci) * 9 * WROW];
    #pragma unroll
    for (int ky = 0; ky < 9; ky++) {
        #pragma unroll
        for (int kx = 0; kx < 9; kx++) {
            float w = ker[ky * 9 + kx] * inv;
            union { float f[2]; u64 q; } u;
            u.f[0] = w; u.f[1] = w;
            dst[ky * WROW + kx] = u.q;
        }
        dst[ky * WROW + 9] = 0ull;   // pad
    }
}

// ---------------------------------------------------------------------------
// cp.async helpers
// ---------------------------------------------------------------------------
__device__ __forceinline__ void cpa16(uint32_t dst, const void* src, int szbytes) {
    asm volatile("cp.async.ca.shared.global [%0], [%1], 16, %2;"
                 :: "r"(dst), "l"(src), "r"(szbytes));
}
__device__ __forceinline__ void cpa8(uint32_t dst, const void* src) {
    asm volatile("cp.async.ca.shared.global [%0], [%1], 8;"
                 :: "r"(dst), "l"(src));
}
__device__ __forceinline__ void cpa_commit() {
    asm volatile("cp.async.commit_group;" ::: "memory");
}
__device__ __forceinline__ void cpa_wait1() {
    asm volatile("cp.async.wait_group 1;" ::: "memory");
}
__device__ __forceinline__ void cpa_wait0() {
    asm volatile("cp.async.wait_group 0;" ::: "memory");
}

// ---------------------------------------------------------------------------
// PTX inner-loop macros with persistent named registers.
// LDROW: load one 12-float tile row, build 6 aligned + 5 odd f32x2 pairs.
// ACCROW(OY, WOFF): load 9 weight pairs for one ky row, 18 packed FMAs.
// ---------------------------------------------------------------------------
#define PTX_DECLS() asm volatile(                                     \
    ".reg .b32 pf<12>;\n\t"                                           \
    ".reg .b64 pA<6>;\n\t"                                            \
    ".reg .b64 pB<5>;\n\t"                                            \
    ".reg .b64 pw<9>;\n\t"                                            \
    ".reg .b64 pc00,pc01,pc10,pc11,pc20,pc21,pc30,pc31;\n\t"          \
    ".reg .u32 ptb,pwb,pta,pwa;\n\t")

#define PTX_ZERO_ACC() asm volatile(                                  \
    "mov.b64 pc00,0; mov.b64 pc01,0;\n\t"                             \
    "mov.b64 pc10,0; mov.b64 pc11,0;\n\t"                             \
    "mov.b64 pc20,0; mov.b64 pc21,0;\n\t"                             \
    "mov.b64 pc30,0; mov.b64 pc31,0;\n\t")

#define LDROW(OFF) asm volatile(                                      \
    "add.u32 pta, ptb, " OFF ";\n\t"                                  \
    "ld.shared.v4.b32 {pf0,pf1,pf2,pf3},[pta];\n\t"                   \
    "ld.shared.v4.b32 {pf4,pf5,pf6,pf7},[pta+16];\n\t"                \
    "ld.shared.v4.b32 {pf8,pf9,pf10,pf11},[pta+32];\n\t"              \
    "mov.b64 pA0,{pf0,pf1};\n\t"                                      \
    "mov.b64 pA1,{pf2,pf3};\n\t"                                      \
    "mov.b64 pA2,{pf4,pf5};\n\t"                                      \
    "mov.b64 pA3,{pf6,pf7};\n\t"                                      \
    "mov.b64 pA4,{pf8,pf9};\n\t"                                      \
    "mov.b64 pA5,{pf10,pf11};\n\t"                                    \
    "mov.b64 pB0,{pf1,pf2};\n\t"                                      \
    "mov.b64 pB1,{pf3,pf4};\n\t"                                      \
    "mov.b64 pB2,{pf5,pf6};\n\t"                                      \
    "mov.b64 pB3,{pf7,pf8};\n\t"                                      \
    "mov.b64 pB4,{pf9,pf10};\n\t")

#define ACCROW(OY, WOFF) asm volatile(                                \
    "add.u32 pwa, pwb, " WOFF ";\n\t"                                 \
    "ld.shared.v2.b64 {pw0,pw1},[pwa];\n\t"                           \
    "ld.shared.v2.b64 {pw2,pw3},[pwa+16];\n\t"                        \
    "ld.shared.v2.b64 {pw4,pw5},[pwa+32];\n\t"                        \
    "ld.shared.v2.b64 {pw6,pw7},[pwa+48];\n\t"                        \
    "ld.shared.b64 pw8,[pwa+64];\n\t"                                 \
    "fma.rn.f32x2 pc" #OY "0, pA0, pw0, pc" #OY "0;\n\t"              \
    "fma.rn.f32x2 pc" #OY "1, pA1, pw0, pc" #OY "1;\n\t"              \
    "fma.rn.f32x2 pc" #OY "0, pB0, pw1, pc" #OY "0;\n\t"              \
    "fma.rn.f32x2 pc" #OY "1, pB1, pw1, pc" #OY "1;\n\t"              \
    "fma.rn.f32x2 pc" #OY "0, pA1, pw2, pc" #OY "0;\n\t"              \
    "fma.rn.f32x2 pc" #OY "1, pA2, pw2, pc" #OY "1;\n\t"              \
    "fma.rn.f32x2 pc" #OY "0, pB1, pw3, pc" #OY "0;\n\t"              \
    "fma.rn.f32x2 pc" #OY "1, pB2, pw3, pc" #OY "1;\n\t"              \
    "fma.rn.f32x2 pc" #OY "0, pA2, pw4, pc" #OY "0;\n\t"              \
    "fma.rn.f32x2 pc" #OY "1, pA3, pw4, pc" #OY "1;\n\t"              \
    "fma.rn.f32x2 pc" #OY "0, pB2, pw5, pc" #OY "0;\n\t"              \
    "fma.rn.f32x2 pc" #OY "1, pB3, pw5, pc" #OY "1;\n\t"              \
    "fma.rn.f32x2 pc" #OY "0, pA3, pw6, pc" #OY "0;\n\t"              \
    "fma.rn.f32x2 pc" #OY "1, pA4, pw6, pc" #OY "1;\n\t"              \
    "fma.rn.f32x2 pc" #OY "0, pB3, pw7, pc" #OY "0;\n\t"              \
    "fma.rn.f32x2 pc" #OY "1, pB4, pw7, pc" #OY "1;\n\t"              \
    "fma.rn.f32x2 pc" #OY "0, pA4, pw8, pc" #OY "0;\n\t"              \
    "fma.rn.f32x2 pc" #OY "1, pA5, pw8, pc" #OY "1;\n\t")

// ---------------------------------------------------------------------------
// Phase 2: direct conv, double-buffered cp.async staging, PTX f32x2 core.
// Block = 256 threads, one (n, co), 64x64 tile, 4x4 outputs/thread.
// ---------------------------------------------------------------------------
__global__ __launch_bounds__(256, 3)
void conv_kernel(const float* __restrict__ x,
                 const float* __restrict__ bias,
                 float* __restrict__ out) {
    __shared__ __align__(16) float tile2[2][TILE_ELEMS];
    __shared__ __align__(16) u64   wsh2[2][9 * WROW];

    const int tid = threadIdx.x;
    const int x0 = blockIdx.x * TILE;
    const int y0 = blockIdx.y * TILE;
    const int n  = blockIdx.z >> 5;
    const int co = blockIdx.z & 31;

    const int ox0 = (tid & 15) * 4;
    const int oy0 = (tid >> 4) * 4;

    const float* xn = x + (size_t)n * CIN * CHW;

    PTX_DECLS();
    PTX_ZERO_ACC();

    // ---- precompute staging offsets: 1296 16B chunks, <=6 per thread ----
    int off[6];
    int szmask = 0;
    #pragma unroll
    for (int k = 0; k < 6; k++) {
        int id = tid + 256 * k;
        off[k] = 0;
        if (id < NCHUNK) {
            int row = id / 18;
            int c4  = (id - row * 18) * 4;
            int gy  = y0 - PADV + row;
            int gx  = x0 - PADV + c4;
            bool ok = ((unsigned)gy < HH) && ((unsigned)gx <= (WW - 4));
            if (ok) {
                off[k] = gy * WW + gx;
                szmask |= 1 << k;
            }
        }
    }
    const u64* wpp = g_w2p + (size_t)co * CIN * 9 * WROW + tid;

    const uint32_t tbs0 = (uint32_t)__cvta_generic_to_shared(&tile2[0][0]);
    const uint32_t tbs1 = (uint32_t)__cvta_generic_to_shared(&tile2[1][0]);
    const uint32_t wbs0 = (uint32_t)__cvta_generic_to_shared(&wsh2[0][0]);
    const uint32_t wbs1 = (uint32_t)__cvta_generic_to_shared(&wsh2[1][0]);

    const int thr_off = (oy0 * SROW + ox0) * 4;   // byte offset of this thread's tile origin

    auto stage = [&](int ci, int buf) {
        const float* xc = xn + (size_t)ci * CHW;
        uint32_t tb = (buf ? tbs1 : tbs0) + tid * 16;
        #pragma unroll
        for (int k = 0; k < 6; k++) {
            if (k < 5 || tid < NCHUNK - 5 * 256) {
                cpa16(tb + k * 4096, xc + off[k], ((szmask >> k) & 1) << 4);
            }
        }
        if (tid < 9 * WROW) {
            cpa8((buf ? wbs1 : wbs0) + tid * 8, wpp + (size_t)ci * 9 * WROW);
        }
    };

    stage(0, 0);
    cpa_commit();

    for (int ci = 0; ci < CIN; ci++) {
        if (ci + 1 < CIN) {
            stage(ci + 1, (ci + 1) & 1);
            cpa_commit();
            cpa_wait1();        // buffer for ci fully landed (this thread)
        } else {
            cpa_wait0();
        }
        __syncthreads();        // all threads' copies visible

        const int buf = ci & 1;
        asm volatile("mov.u32 ptb, %0;\n\tmov.u32 pwb, %1;\n\t"
                     :: "r"((buf ? tbs1 : tbs0) + thr_off),
                        "r"(buf ? wbs1 : wbs0));

        LDROW("0");    ACCROW(0, "0");
        LDROW("288");  ACCROW(0, "80");  ACCROW(1, "0");
        LDROW("576");  ACCROW(0, "160"); ACCROW(1, "80");  ACCROW(2, "0");
        LDROW("864");  ACCROW(0, "240"); ACCROW(1, "160"); ACCROW(2, "80");  ACCROW(3, "0");
        LDROW("1152"); ACCROW(0, "320"); ACCROW(1, "240"); ACCROW(2, "160"); ACCROW(3, "80");
        LDROW("1440"); ACCROW(0, "400"); ACCROW(1, "320"); ACCROW(2, "240"); ACCROW(3, "160");
        LDROW("1728"); ACCROW(0, "480"); ACCROW(1, "400"); ACCROW(2, "320"); ACCROW(3, "240");
        LDROW("2016"); ACCROW(0, "560"); ACCROW(1, "480"); ACCROW(2, "400"); ACCROW(3, "320");
        LDROW("2304"); ACCROW(0, "640"); ACCROW(1, "560"); ACCROW(2, "480"); ACCROW(3, "400");
        LDROW("2592");                   ACCROW(1, "640"); ACCROW(2, "560"); ACCROW(3, "480");
        LDROW("2880");                                     ACCROW(2, "640"); ACCROW(3, "560");
        LDROW("3168");                                                       ACCROW(3, "640");

        __syncthreads();        // compute on buf done before it is re-staged
    }

    // ---- readout + bias + store ----
    float v[16];
    asm volatile("mov.b64 {%0,%1}, pc00;\n\tmov.b64 {%2,%3}, pc01;\n\t"
                 : "=f"(v[0]), "=f"(v[1]), "=f"(v[2]), "=f"(v[3]));
    asm volatile("mov.b64 {%0,%1}, pc10;\n\tmov.b64 {%2,%3}, pc11;\n\t"
                 : "=f"(v[4]), "=f"(v[5]), "=f"(v[6]), "=f"(v[7]));
    asm volatile("mov.b64 {%0,%1}, pc20;\n\tmov.b64 {%2,%3}, pc21;\n\t"
                 : "=f"(v[8]), "=f"(v[9]), "=f"(v[10]), "=f"(v[11]));
    asm volatile("mov.b64 {%0,%1}, pc30;\n\tmov.b64 {%2,%3}, pc31;\n\t"
                 : "=f"(v[12]), "=f"(v[13]), "=f"(v[14]), "=f"(v[15]));

    const float bv = bias[co];
    float* op = out + (((size_t)(n * COUT + co) * HH + (y0 + oy0)) * WW + x0 + ox0);
    #pragma unroll
    for (int oy = 0; oy < 4; oy++) {
        float4 ov = make_float4(v[oy * 4 + 0] + bv, v[oy * 4 + 1] + bv,
                                v[oy * 4 + 2] + bv, v[oy * 4 + 3] + bv);
        *(float4*)(op + (size_t)oy * WW) = ov;
    }
}

// ---------------------------------------------------------------------------
extern "C" void kernel_launch(void* const* d_in, const int* in_sizes, int n_in,
                              void* d_out, int out_size) {
    const float* x    = (const float*)d_in[0];   // [16, 32, 192, 192]
    const float* wp   = (const float*)d_in[1];   // [32, 32, 3]
    const float* bias = (const float*)d_in[2];   // [32]
    float* out = (float*)d_out;                  // [16, 32, 192, 192]

    gk_compute<<<COUT, CIN>>>(wp);

    dim3 grid(WW / TILE, HH / TILE, NB * COUT);  // (3, 3, 512)
    dim3 blk(256);
    conv_kernel<<<grid, blk>>>(x, bias, out);
}

// round 8
// speedup vs baseline: 1.0014x; 1.0014x over previous
#include <cuda_runtime.h>
#include <cstdint>

#define KS    9
#define PADV  4
#define CIN   32
#define COUT  32
#define HH    192
#define WW    192
#define NB    16
#define CHW   (HH * WW)

#define TILE  64
#define SROW  72                 // 64 + 8 halo
#define TILE_ELEMS (SROW * SROW) // 5184 floats = 1296 16B chunks
#define NCHUNK 1296
#define WROW  10                 // 9 taps padded to 10 u64 (16B alignment)

typedef unsigned long long u64;

// Precomputed Gaussian kernels, duplicated as {w,w} u64 pairs, rows padded to 10.
__device__ u64 g_w2p[COUT * CIN * 9 * WROW];

// ---------------------------------------------------------------------------
// Phase 1: build normalized anisotropic Gaussian kernels from (sx, sy, theta)
// ---------------------------------------------------------------------------
__global__ void gk_compute(const float* __restrict__ wp) {
    int co = blockIdx.x;
    int ci = threadIdx.x;
    const float* p = wp + (co * CIN + ci) * 3;
    float sx = p[0], sy = p[1], th = p[2];
    float rad = th * 0.017453292519943295f;   // th / 180 * pi
    float c = cosf(rad), s = sinf(rad);
    float sx2 = sx * sx, sy2 = sy * sy;
    float a = c * c * sx2 + s * s * sy2;
    float b = c * s * (sx2 - sy2);
    float d = s * s * sx2 + c * c * sy2;
    float det = a * d - b * b;
    float ia = d / det, ib = -b / det, idd = a / det;

    float ker[81];
    float sum = 0.f;
    #pragma unroll
    for (int ky = 0; ky < 9; ky++) {
        float yy = (float)(ky - 4);
        #pragma unroll
        for (int kx = 0; kx < 9; kx++) {
            float xx = (float)(kx - 4);
            float q = ia * xx * xx + 2.0f * ib * xx * yy + idd * yy * yy;
            float v = expf(-0.5f * q);
            ker[ky * 9 + kx] = v;
            sum += v;
        }
    }
    float inv = 1.0f / sum;
    u64* dst = &g_w2p[(co * CIN + ci) * 9 * WROW];
    #pragma unroll
    for (int ky = 0; ky < 9; ky++) {
        #pragma unroll
        for (int kx = 0; kx < 9; kx++) {
            float w = ker[ky * 9 + kx] * inv;
            union { float f[2]; u64 q; } u;
            u.f[0] = w; u.f[1] = w;
            dst[ky * WROW + kx] = u.q;
        }
        dst[ky * WROW + 9] = 0ull;   // pad
    }
}

// ---------------------------------------------------------------------------
// cp.async helpers
// ---------------------------------------------------------------------------
__device__ __forceinline__ void cpa16(uint32_t dst, const void* src, int szbytes) {
    asm volatile("cp.async.ca.shared.global [%0], [%1], 16, %2;"
                 :: "r"(dst), "l"(src), "r"(szbytes));
}
__device__ __forceinline__ void cpa8(uint32_t dst, const void* src) {
    asm volatile("cp.async.ca.shared.global [%0], [%1], 8;"
                 :: "r"(dst), "l"(src));
}
__device__ __forceinline__ void cpa_commit() {
    asm volatile("cp.async.commit_group;" ::: "memory");
}
__device__ __forceinline__ void cpa_wait1() {
    asm volatile("cp.async.wait_group 1;" ::: "memory");
}
__device__ __forceinline__ void cpa_wait0() {
    asm volatile("cp.async.wait_group 0;" ::: "memory");
}

// ---------------------------------------------------------------------------
// PTX inner-loop macros with persistent named registers.
// LDROW: load one 12-float tile row, build 6 aligned + 5 odd f32x2 pairs.
// ACCROW(OY, WOFF): load 9 weight pairs for one ky row, 18 packed FMAs.
// ---------------------------------------------------------------------------
#define PTX_DECLS() asm volatile(                                     \
    ".reg .b32 pf<12>;\n\t"                                           \
    ".reg .b64 pA<6>;\n\t"                                            \
    ".reg .b64 pB<5>;\n\t"                                            \
    ".reg .b64 pw<9>;\n\t"                                            \
    ".reg .b64 pc00,pc01,pc10,pc11,pc20,pc21,pc30,pc31;\n\t"          \
    ".reg .u32 ptb,pwb,pta,pwa;\n\t")

#define PTX_ZERO_ACC() asm volatile(                                  \
    "mov.b64 pc00,0; mov.b64 pc01,0;\n\t"                             \
    "mov.b64 pc10,0; mov.b64 pc11,0;\n\t"                             \
    "mov.b64 pc20,0; mov.b64 pc21,0;\n\t"                             \
    "mov.b64 pc30,0; mov.b64 pc31,0;\n\t")

#define LDROW(OFF) asm volatile(                                      \
    "add.u32 pta, ptb, " OFF ";\n\t"                                  \
    "ld.shared.v4.b32 {pf0,pf1,pf2,pf3},[pta];\n\t"                   \
    "ld.shared.v4.b32 {pf4,pf5,pf6,pf7},[pta+16];\n\t"                \
    "ld.shared.v4.b32 {pf8,pf9,pf10,pf11},[pta+32];\n\t"              \
    "mov.b64 pA0,{pf0,pf1};\n\t"                                      \
    "mov.b64 pA1,{pf2,pf3};\n\t"                                      \
    "mov.b64 pA2,{pf4,pf5};\n\t"                                      \
    "mov.b64 pA3,{pf6,pf7};\n\t"                                      \
    "mov.b64 pA4,{pf8,pf9};\n\t"                                      \
    "mov.b64 pA5,{pf10,pf11};\n\t"                                    \
    "mov.b64 pB0,{pf1,pf2};\n\t"                                      \
    "mov.b64 pB1,{pf3,pf4};\n\t"                                      \
    "mov.b64 pB2,{pf5,pf6};\n\t"                                      \
    "mov.b64 pB3,{pf7,pf8};\n\t"                                      \
    "mov.b64 pB4,{pf9,pf10};\n\t")

#define ACCROW(OY, WOFF) asm volatile(                                \
    "add.u32 pwa, pwb, " WOFF ";\n\t"                                 \
    "ld.shared.v2.b64 {pw0,pw1},[pwa];\n\t"                           \
    "ld.shared.v2.b64 {pw2,pw3},[pwa+16];\n\t"                        \
    "ld.shared.v2.b64 {pw4,pw5},[pwa+32];\n\t"                        \
    "ld.shared.v2.b64 {pw6,pw7},[pwa+48];\n\t"                        \
    "ld.shared.b64 pw8,[pwa+64];\n\t"                                 \
    "fma.rn.f32x2 pc" #OY "0, pA0, pw0, pc" #OY "0;\n\t"              \
    "fma.rn.f32x2 pc" #OY "1, pA1, pw0, pc" #OY "1;\n\t"              \
    "fma.rn.f32x2 pc" #OY "0, pB0, pw1, pc" #OY "0;\n\t"              \
    "fma.rn.f32x2 pc" #OY "1, pB1, pw1, pc" #OY "1;\n\t"              \
    "fma.rn.f32x2 pc" #OY "0, pA1, pw2, pc" #OY "0;\n\t"              \
    "fma.rn.f32x2 pc" #OY "1, pA2, pw2, pc" #OY "1;\n\t"              \
    "fma.rn.f32x2 pc" #OY "0, pB1, pw3, pc" #OY "0;\n\t"              \
    "fma.rn.f32x2 pc" #OY "1, pB2, pw3, pc" #OY "1;\n\t"              \
    "fma.rn.f32x2 pc" #OY "0, pA2, pw4, pc" #OY "0;\n\t"              \
    "fma.rn.f32x2 pc" #OY "1, pA3, pw4, pc" #OY "1;\n\t"              \
    "fma.rn.f32x2 pc" #OY "0, pB2, pw5, pc" #OY "0;\n\t"              \
    "fma.rn.f32x2 pc" #OY "1, pB3, pw5, pc" #OY "1;\n\t"              \
    "fma.rn.f32x2 pc" #OY "0, pA3, pw6, pc" #OY "0;\n\t"              \
    "fma.rn.f32x2 pc" #OY "1, pA4, pw6, pc" #OY "1;\n\t"              \
    "fma.rn.f32x2 pc" #OY "0, pB3, pw7, pc" #OY "0;\n\t"              \
    "fma.rn.f32x2 pc" #OY "1, pB4, pw7, pc" #OY "1;\n\t"              \
    "fma.rn.f32x2 pc" #OY "0, pA4, pw8, pc" #OY "0;\n\t"              \
    "fma.rn.f32x2 pc" #OY "1, pA5, pw8, pc" #OY "1;\n\t")

// ---------------------------------------------------------------------------
// Phase 2: direct conv, double-buffered cp.async staging, PTX f32x2 core.
// Block = 256 threads, one (n, co), 64x64 tile, 4x4 outputs/thread.
// ---------------------------------------------------------------------------
__global__ __launch_bounds__(256, 3)
void conv_kernel(const float* __restrict__ x,
                 const float* __restrict__ bias,
                 float* __restrict__ out) {
    __shared__ __align__(16) float tile2[2][TILE_ELEMS];
    __shared__ __align__(16) u64   wsh2[2][9 * WROW];

    const int tid = threadIdx.x;
    const int x0 = blockIdx.x * TILE;
    const int y0 = blockIdx.y * TILE;
    const int n  = blockIdx.z >> 5;
    const int co = blockIdx.z & 31;

    const int ox0 = (tid & 15) * 4;
    const int oy0 = (tid >> 4) * 4;

    const float* xn = x + (size_t)n * CIN * CHW;

    PTX_DECLS();
    PTX_ZERO_ACC();

    // ---- precompute staging offsets: 1296 16B chunks, <=6 per thread ----
    int off[6];
    int szmask = 0;
    #pragma unroll
    for (int k = 0; k < 6; k++) {
        int id = tid + 256 * k;
        off[k] = 0;
        if (id < NCHUNK) {
            int row = id / 18;
            int c4  = (id - row * 18) * 4;
            int gy  = y0 - PADV + row;
            int gx  = x0 - PADV + c4;
            bool ok = ((unsigned)gy < HH) && ((unsigned)gx <= (WW - 4));
            if (ok) {
                off[k] = gy * WW + gx;
                szmask |= 1 << k;
            }
        }
    }
    const u64* wpp = g_w2p + (size_t)co * CIN * 9 * WROW + tid;

    const uint32_t tbs0 = (uint32_t)__cvta_generic_to_shared(&tile2[0][0]);
    const uint32_t tbs1 = (uint32_t)__cvta_generic_to_shared(&tile2[1][0]);
    const uint32_t wbs0 = (uint32_t)__cvta_generic_to_shared(&wsh2[0][0]);
    const uint32_t wbs1 = (uint32_t)__cvta_generic_to_shared(&wsh2[1][0]);

    const int thr_off = (oy0 * SROW + ox0) * 4;   // byte offset of this thread's tile origin

    auto stage = [&](int ci, int buf) {
        const float* xc = xn + (size_t)ci * CHW;
        uint32_t tb = (buf ? tbs1 : tbs0) + tid * 16;
        #pragma unroll
        for (int k = 0; k < 6; k++) {
            if (k < 5 || tid < NCHUNK - 5 * 256) {
                cpa16(tb + k * 4096, xc + off[k], ((szmask >> k) & 1) << 4);
            }
        }
        if (tid < 9 * WROW) {
            cpa8((buf ? wbs1 : wbs0) + tid * 8, wpp + (size_t)ci * 9 * WROW);
        }
    };

    stage(0, 0);
    cpa_commit();

    for (int ci = 0; ci < CIN; ci++) {
        if (ci + 1 < CIN) {
            stage(ci + 1, (ci + 1) & 1);
            cpa_commit();
            cpa_wait1();        // buffer for ci fully landed (this thread)
        } else {
            cpa_wait0();
        }
        __syncthreads();        // all threads' copies visible

        const int buf = ci & 1;
        asm volatile("mov.u32 ptb, %0;\n\tmov.u32 pwb, %1;\n\t"
                     :: "r"((buf ? tbs1 : tbs0) + thr_off),
                        "r"(buf ? wbs1 : wbs0));

        LDROW("0");    ACCROW(0, "0");
        LDROW("288");  ACCROW(0, "80");  ACCROW(1, "0");
        LDROW("576");  ACCROW(0, "160"); ACCROW(1, "80");  ACCROW(2, "0");
        LDROW("864");  ACCROW(0, "240"); ACCROW(1, "160"); ACCROW(2, "80");  ACCROW(3, "0");
        LDROW("1152"); ACCROW(0, "320"); ACCROW(1, "240"); ACCROW(2, "160"); ACCROW(3, "80");
        LDROW("1440"); ACCROW(0, "400"); ACCROW(1, "320"); ACCROW(2, "240"); ACCROW(3, "160");
        LDROW("1728"); ACCROW(0, "480"); ACCROW(1, "400"); ACCROW(2, "320"); ACCROW(3, "240");
        LDROW("2016"); ACCROW(0, "560"); ACCROW(1, "480"); ACCROW(2, "400"); ACCROW(3, "320");
        LDROW("2304"); ACCROW(0, "640"); ACCROW(1, "560"); ACCROW(2, "480"); ACCROW(3, "400");
        LDROW("2592");                   ACCROW(1, "640"); ACCROW(2, "560"); ACCROW(3, "480");
        LDROW("2880");                                     ACCROW(2, "640"); ACCROW(3, "560");
        LDROW("3168");                                                       ACCROW(3, "640");

        __syncthreads();        // compute on buf done before it is re-staged
    }

    // ---- readout + bias + store ----
    float v[16];
    asm volatile("mov.b64 {%0,%1}, pc00;\n\tmov.b64 {%2,%3}, pc01;\n\t"
                 : "=f"(v[0]), "=f"(v[1]), "=f"(v[2]), "=f"(v[3]));
    asm volatile("mov.b64 {%0,%1}, pc10;\n\tmov.b64 {%2,%3}, pc11;\n\t"
                 : "=f"(v[4]), "=f"(v[5]), "=f"(v[6]), "=f"(v[7]));
    asm volatile("mov.b64 {%0,%1}, pc20;\n\tmov.b64 {%2,%3}, pc21;\n\t"
                 : "=f"(v[8]), "=f"(v[9]), "=f"(v[10]), "=f"(v[11]));
    asm volatile("mov.b64 {%0,%1}, pc30;\n\tmov.b64 {%2,%3}, pc31;\n\t"
                 : "=f"(v[12]), "=f"(v[13]), "=f"(v[14]), "=f"(v[15]));

    const float bv = bias[co];
    float* op = out + (((size_t)(n * COUT + co) * HH + (y0 + oy0)) * WW + x0 + ox0);
    #pragma unroll
    for (int oy = 0; oy < 4; oy++) {
        float4 ov = make_float4(v[oy * 4 + 0] + bv, v[oy * 4 + 1] + bv,
                                v[oy * 4 + 2] + bv, v[oy * 4 + 3] + bv);
        *(float4*)(op + (size_t)oy * WW) = ov;
    }
}

// ---------------------------------------------------------------------------
extern "C" void kernel_launch(void* const* d_in, const int* in_sizes, int n_in,
                              void* d_out, int out_size) {
    const float* x    = (const float*)d_in[0];   // [16, 32, 192, 192]
    const float* wp   = (const float*)d_in[1];   // [32, 32, 3]
    const float* bias = (const float*)d_in[2];   // [32]
    float* out = (float*)d_out;                  // [16, 32, 192, 192]

    gk_compute<<<COUT, CIN>>>(wp);

    dim3 grid(WW / TILE, HH / TILE, NB * COUT);  // (3, 3, 512)
    dim3 blk(256);
    conv_kernel<<<grid, blk>>>(x, bias, out);
}

// round 10
// speedup vs baseline: 4.5820x; 4.5754x over previous
#include <cuda_runtime.h>
#include <cuda_fp16.h>
#include <cstdint>

typedef unsigned long long u64;

#define CIN   32
#define COUT  32
#define HH    192
#define WW    192
#define NB    16
#define HWP   (HH * WW)          // 36864
#define NPIX  (NB * HWP)
#define NTAP  81

// NHWC fp16 copy of input: [n][y][x][ci], 64B per pixel
__device__ __align__(16) __half g_xh[(size_t)NPIX * CIN];
// B fragments in mma register layout: [tap][kchunk 2][ntile 4][lane 32] u64 {b0,b1}
__device__ __align__(16) u64 g_wf[NTAP * 2 * 4 * 32];

// ---------------------------------------------------------------------------
// Prep 1: Gaussian kernels -> B fragments (one thread per (co, ci))
// ---------------------------------------------------------------------------
__global__ void gk_compute(const float* __restrict__ wp) {
    int co = blockIdx.x;
    int ci = threadIdx.x;
    const float* p = wp + (co * CIN + ci) * 3;
    float sx = p[0], sy = p[1], th = p[2];
    float rad = th * 0.017453292519943295f;   // th / 180 * pi (matches reference)
    float c = cosf(rad), s = sinf(rad);
    float sx2 = sx * sx, sy2 = sy * sy;
    float a = c * c * sx2 + s * s * sy2;
    float b = c * s * (sx2 - sy2);
    float d = s * s * sx2 + c * c * sy2;
    float det = a * d - b * b;
    float ia = d / det, ib = -b / det, idd = a / det;

    float ker[NTAP];
    float sum = 0.f;
    #pragma unroll
    for (int ky = 0; ky < 9; ky++) {
        float yy = (float)(ky - 4);
        #pragma unroll
        for (int kx = 0; kx < 9; kx++) {
            float xx = (float)(kx - 4);
            float q = ia * xx * xx + 2.0f * ib * xx * yy + idd * yy * yy;
            float v = expf(-0.5f * q);
            ker[ky * 9 + kx] = v;
            sum += v;
        }
    }
    float inv = 1.0f / sum;

    // B[k=ci][n=co]: fragment slot for (co, ci)
    int k     = ci >> 4;            // kchunk
    int kk    = ci & 15;            // row within 16
    int lane4 = (kk & 7) >> 1;      // threadID_in_group
    int sel   = ((kk >> 3) << 1) | (kk & 1);   // which half within {b0,b1}
    size_t idx = (((size_t)0 * 2 + k) * 4 + (co >> 3)) * 32 + ((co & 7) << 2) + lane4;
    __half* wf = (__half*)g_wf;
    #pragma unroll
    for (int t = 0; t < NTAP; t++) {
        wf[((size_t)t * 256 + idx) * 4 + sel] = __float2half_rn(ker[t] * inv);
    }
}

// ---------------------------------------------------------------------------
// Prep 2: NCHW fp32 -> NHWC fp16
// grid (192/32, 192, 16), block (32, 8)
// ---------------------------------------------------------------------------
__global__ void nchw_to_nhwc_h(const float* __restrict__ x) {
    __shared__ float t[32][33];
    const int x0 = blockIdx.x * 32;
    const int y  = blockIdx.y;
    const int n  = blockIdx.z;
    const float* src = x + (size_t)n * CIN * HWP + (size_t)y * WW + x0;
    #pragma unroll
    for (int ci = threadIdx.y; ci < 32; ci += 8)
        t[ci][threadIdx.x] = src[(size_t)ci * HWP + threadIdx.x];
    __syncthreads();
    const int tid = threadIdx.y * 32 + threadIdx.x;
    const int pix = tid >> 3;
    const int cg  = (tid & 7) * 4;
    __half2 h0 = __floats2half2_rn(t[cg + 0][pix], t[cg + 1][pix]);
    __half2 h1 = __floats2half2_rn(t[cg + 2][pix], t[cg + 3][pix]);
    uint2 v;
    v.x = *(uint32_t*)&h0;
    v.y = *(uint32_t*)&h1;
    *(uint2*)(g_xh + ((size_t)n * HWP + (size_t)y * WW + x0 + pix) * 32 + cg) = v;
}

// ---------------------------------------------------------------------------
// HMMA m16n8k16 f16 -> f32
// ---------------------------------------------------------------------------
__device__ __forceinline__ void mma16816(float* d,
                                         uint32_t a0, uint32_t a1, uint32_t a2, uint32_t a3,
                                         uint32_t b0, uint32_t b1) {
    asm volatile(
        "mma.sync.aligned.m16n8k16.row.col.f32.f16.f16.f32 "
        "{%0,%1,%2,%3},{%4,%5,%6,%7},{%8,%9},{%0,%1,%2,%3};"
        : "+f"(d[0]), "+f"(d[1]), "+f"(d[2]), "+f"(d[3])
        : "r"(a0), "r"(a1), "r"(a2), "r"(a3), "r"(b0), "r"(b1));
}

// ---------------------------------------------------------------------------
// Main: implicit conv, one warp = 16 consecutive pixels of one row,
// D[16 x 32] accumulated over 81 taps. 8 warps/block = 8 adjacent rows.
// ---------------------------------------------------------------------------
__global__ __launch_bounds__(256)
void conv_mma(const float* __restrict__ bias, float* __restrict__ out) {
    const int warp = threadIdx.x >> 5;
    const int lane = threadIdx.x & 31;
    const int b  = blockIdx.x;
    const int x0 = (b % 12) * 16;
    const int y  = ((b / 12) % 24) * 8 + warp;
    const int n  = b / 288;

    const int g  = lane >> 2;          // groupID: pixel rows g, g+8
    const int c0 = (lane & 3) * 2;     // ci base (halves)

    float d[4][4] = {};                // 4 ntiles x 4 accum

    const __half* xb = g_xh + (size_t)n * HWP * 32;
    const int pA = x0 + g;

    #pragma unroll 1
    for (int dy = 0; dy < 9; dy++) {
        const int  yy = y + dy - 4;
        const bool vy = (unsigned)yy < (unsigned)HH;
        const __half* rb = xb + (size_t)yy * WW * 32;
        #pragma unroll 1
        for (int dx = 0; dx < 9; dx++) {
            const int  xa = pA + dx - 4;
            const int  xc = xa + 8;
            const bool va = vy && ((unsigned)xa < (unsigned)WW);
            const bool vb = vy && ((unsigned)xc < (unsigned)WW);

            uint32_t A[8] = {0, 0, 0, 0, 0, 0, 0, 0};
            if (va) {
                const uint32_t* q = (const uint32_t*)(rb + xa * 32 + c0);
                A[0] = q[0]; A[2] = q[4]; A[4] = q[8]; A[6] = q[12];
            }
            if (vb) {
                const uint32_t* q = (const uint32_t*)(rb + xc * 32 + c0);
                A[1] = q[0]; A[3] = q[4]; A[5] = q[8]; A[7] = q[12];
            }

            const int tap = dy * 9 + dx;
            const uint2* wf = (const uint2*)g_wf + tap * 256 + lane;
            #pragma unroll
            for (int nt = 0; nt < 4; nt++) {
                uint2 b0 = wf[nt * 32];          // kchunk 0
                uint2 b1 = wf[128 + nt * 32];    // kchunk 1
                mma16816(d[nt], A[0], A[1], A[2], A[3], b0.x, b0.y);
                mma16816(d[nt], A[4], A[5], A[6], A[7], b1.x, b1.y);
            }
        }
    }

    // epilogue: D mapping: d0 (row g, col c0), d1 (g, c0+1), d2 (g+8, c0), d3 (g+8, c0+1)
    float* ob = out + (size_t)n * COUT * HWP + (size_t)y * WW;
    #pragma unroll
    for (int nt = 0; nt < 4; nt++) {
        const int co0 = nt * 8 + c0;
        const float bv0 = bias[co0], bv1 = bias[co0 + 1];
        ob[(size_t)co0 * HWP + x0 + g]           = d[nt][0] + bv0;
        ob[(size_t)(co0 + 1) * HWP + x0 + g]     = d[nt][1] + bv1;
        ob[(size_t)co0 * HWP + x0 + g + 8]       = d[nt][2] + bv0;
        ob[(size_t)(co0 + 1) * HWP + x0 + g + 8] = d[nt][3] + bv1;
    }
}

// ---------------------------------------------------------------------------
extern "C" void kernel_launch(void* const* d_in, const int* in_sizes, int n_in,
                              void* d_out, int out_size) {
    const float* x    = (const float*)d_in[0];   // [16, 32, 192, 192]
    const float* wp   = (const float*)d_in[1];   // [32, 32, 3]
    const float* bias = (const float*)d_in[2];   // [32]
    float* out = (float*)d_out;                  // [16, 32, 192, 192]

    gk_compute<<<COUT, CIN>>>(wp);
    nchw_to_nhwc_h<<<dim3(WW / 32, HH, NB), dim3(32, 8)>>>(x);
    conv_mma<<<NB * 24 * 12, 256>>>(bias, out);  // 4608 blocks, 8 warps each
}

// round 11
// speedup vs baseline: 9.0739x; 1.9803x over previous
#include <cuda_runtime.h>
#include <cuda_fp16.h>
#include <cstdint>

typedef unsigned long long u64;

#define CIN   32
#define COUT  32
#define HH    192
#define WW    192
#define NB    16
#define HWP   (HH * WW)          // 36864
#define NPIX  (NB * HWP)
#define NTAP  81

// NHWC fp16 copy of input: [n][y][x][ci], 64B per pixel
__device__ __align__(16) __half g_xh[(size_t)NPIX * CIN];
// B fragments in mma register layout: [tap][kchunk 2][ntile 4][lane 32] u64 {b0,b1}
__device__ __align__(16) u64 g_wf[NTAP * 2 * 4 * 32];

// ---------------------------------------------------------------------------
// Prep 1: Gaussian kernels -> B fragments (one thread per (co, ci))
// ---------------------------------------------------------------------------
__global__ void gk_compute(const float* __restrict__ wp) {
    int co = blockIdx.x;
    int ci = threadIdx.x;
    const float* p = wp + (co * CIN + ci) * 3;
    float sx = p[0], sy = p[1], th = p[2];
    float rad = th * 0.017453292519943295f;   // th / 180 * pi (matches reference)
    float c = cosf(rad), s = sinf(rad);
    float sx2 = sx * sx, sy2 = sy * sy;
    float a = c * c * sx2 + s * s * sy2;
    float b = c * s * (sx2 - sy2);
    float d = s * s * sx2 + c * c * sy2;
    float det = a * d - b * b;
    float ia = d / det, ib = -b / det, idd = a / det;

    float ker[NTAP];
    float sum = 0.f;
    #pragma unroll
    for (int ky = 0; ky < 9; ky++) {
        float yy = (float)(ky - 4);
        #pragma unroll
        for (int kx = 0; kx < 9; kx++) {
            float xx = (float)(kx - 4);
            float q = ia * xx * xx + 2.0f * ib * xx * yy + idd * yy * yy;
            float v = expf(-0.5f * q);
            ker[ky * 9 + kx] = v;
            sum += v;
        }
    }
    float inv = 1.0f / sum;

    // B[k=ci][n=co]: fragment slot for (co, ci)
    int k     = ci >> 4;            // kchunk
    int kk    = ci & 15;            // row within 16
    int lane4 = (kk & 7) >> 1;      // threadID_in_group
    int sel   = ((kk >> 3) << 1) | (kk & 1);   // which half within {b0,b1}
    size_t idx = (((size_t)0 * 2 + k) * 4 + (co >> 3)) * 32 + ((co & 7) << 2) + lane4;
    __half* wf = (__half*)g_wf;
    #pragma unroll
    for (int t = 0; t < NTAP; t++) {
        wf[((size_t)t * 256 + idx) * 4 + sel] = __float2half_rn(ker[t] * inv);
    }
}

// ---------------------------------------------------------------------------
// Prep 2: NCHW fp32 -> NHWC fp16
// grid (192/32, 192, 16), block (32, 8)
// ---------------------------------------------------------------------------
__global__ void nchw_to_nhwc_h(const float* __restrict__ x) {
    __shared__ float t[32][33];
    const int x0 = blockIdx.x * 32;
    const int y  = blockIdx.y;
    const int n  = blockIdx.z;
    const float* src = x + (size_t)n * CIN * HWP + (size_t)y * WW + x0;
    #pragma unroll
    for (int ci = threadIdx.y; ci < 32; ci += 8)
        t[ci][threadIdx.x] = src[(size_t)ci * HWP + threadIdx.x];
    __syncthreads();
    const int tid = threadIdx.y * 32 + threadIdx.x;
    const int pix = tid >> 3;
    const int cg  = (tid & 7) * 4;
    __half2 h0 = __floats2half2_rn(t[cg + 0][pix], t[cg + 1][pix]);
    __half2 h1 = __floats2half2_rn(t[cg + 2][pix], t[cg + 3][pix]);
    uint2 v;
    v.x = *(uint32_t*)&h0;
    v.y = *(uint32_t*)&h1;
    *(uint2*)(g_xh + ((size_t)n * HWP + (size_t)y * WW + x0 + pix) * 32 + cg) = v;
}

// ---------------------------------------------------------------------------
// helpers
// ---------------------------------------------------------------------------
__device__ __forceinline__ uint32_t smem_u32(const void* p) {
    uint32_t a;
    asm("{ .reg .u64 t; cvta.to.shared.u64 t, %1; cvt.u32.u64 %0, t; }"
        : "=r"(a) : "l"(p));
    return a;
}
__device__ __forceinline__ void cpa16(uint32_t dst, const void* src, int szbytes) {
    asm volatile("cp.async.ca.shared.global [%0], [%1], 16, %2;"
                 :: "r"(dst), "l"(src), "r"(szbytes) : "memory");
}
__device__ __forceinline__ void mma16816(float* d,
                                         uint32_t a0, uint32_t a1, uint32_t a2, uint32_t a3,
                                         uint32_t b0, uint32_t b1) {
    asm volatile(
        "mma.sync.aligned.m16n8k16.row.col.f32.f16.f16.f32 "
        "{%0,%1,%2,%3},{%4,%5,%6,%7},{%8,%9},{%0,%1,%2,%3};"
        : "+f"(d[0]), "+f"(d[1]), "+f"(d[2]), "+f"(d[3])
        : "r"(a0), "r"(a1), "r"(a2), "r"(a3), "r"(b0), "r"(b1));
}
__device__ __forceinline__ void ldmat4(uint32_t* r, uint32_t addr) {
    asm volatile("ldmatrix.sync.aligned.m8n8.x4.shared.b16 {%0,%1,%2,%3}, [%4];"
                 : "=r"(r[0]), "=r"(r[1]), "=r"(r[2]), "=r"(r[3]) : "r"(addr));
}

// smem strip geometry: 16 rows x 40 pixels x 64B, 16B-segment swizzled
#define SPXB   64                  // bytes per pixel
#define SROWB  (40 * SPXB)         // 2560 B per row
#define SSIZE  (16 * SROWB)        // 40960 B
__device__ __forceinline__ uint32_t sw_off(int p, int seg) {
    return (uint32_t)(p * 64 + ((seg ^ ((p >> 1) & 3)) << 4));
}

// ---------------------------------------------------------------------------
// Main: implicit conv. Block = 8 warps, covers 8 rows x 32 pixels.
// Warp w = row y0+w, 32 pixels (2 m16 tiles), D[32 x 32co] in registers.
// Input strip staged in smem once; A fragments via swizzled ldmatrix.x4.
// ---------------------------------------------------------------------------
__global__ __launch_bounds__(256, 2)
void conv_mma(const float* __restrict__ bias, float* __restrict__ out) {
    __shared__ __align__(16) char smem[SSIZE];

    const int tid  = threadIdx.x;
    const int warp = tid >> 5;
    const int lane = tid & 31;
    const int x0 = blockIdx.x * 32;
    const int y0 = blockIdx.y * 8;
    const int n  = blockIdx.z;

    const uint32_t sb = smem_u32(smem);

    // ---- stage 16 rows x 40 px (zfill OOB) : 2560 x 16B chunks, 10/thread ----
    {
        const __half* xb = g_xh + (size_t)n * HWP * 32;
        #pragma unroll
        for (int k = 0; k < 10; k++) {
            int i   = tid + k * 256;
            int row = i / 160;
            int rem = i - row * 160;
            int p   = rem >> 2;
            int seg = rem & 3;
            int gy  = y0 - 4 + row;
            int gx  = x0 - 4 + p;
            bool ok = ((unsigned)gy < HH) && ((unsigned)gx < WW);
            const __half* src = ok ? xb + ((size_t)gy * WW + gx) * 32 + seg * 8 : (const __half*)g_xh;
            cpa16(sb + row * SROWB + sw_off(p, seg), src, ok ? 16 : 0);
        }
        asm volatile("cp.async.commit_group;" ::: "memory");
        asm volatile("cp.async.wait_group 0;" ::: "memory");
        __syncthreads();
    }

    // ldmatrix lane geometry: mat = lane>>3, row_in_mat = lane&7
    // pixel offset pl, segment half sh
    const int pl = (lane & 7) + ((lane >> 3) & 1) * 8;
    const int sh = lane >> 4;

    float d[2][4][4] = {};

    #pragma unroll 1
    for (int dy = 0; dy < 9; dy++) {
        const uint32_t rowb = sb + (warp + dy) * SROWB;
        #pragma unroll 1
        for (int dx = 0; dx < 9; dx++) {
            uint32_t A[2][2][4];
            #pragma unroll
            for (int m = 0; m < 2; m++) {
                const int p = dx + m * 16 + pl;
                #pragma unroll
                for (int kc = 0; kc < 2; kc++) {
                    ldmat4(A[m][kc], rowb + sw_off(p, kc * 2 + sh));
                }
            }

            const int tap = dy * 9 + dx;
            const uint2* wf = (const uint2*)g_wf + tap * 256 + lane;
            #pragma unroll
            for (int nt = 0; nt < 4; nt++) {
                uint2 b0 = wf[nt * 32];          // kchunk 0
                uint2 b1 = wf[128 + nt * 32];    // kchunk 1
                #pragma unroll
                for (int m = 0; m < 2; m++) {
                    mma16816(d[m][nt], A[m][0][0], A[m][0][1], A[m][0][2], A[m][0][3], b0.x, b0.y);
                    mma16816(d[m][nt], A[m][1][0], A[m][1][1], A[m][1][2], A[m][1][3], b1.x, b1.y);
                }
            }
        }
    }

    // ---- epilogue: D rows = pixels, cols = co ----
    const int g  = lane >> 2;
    const int c0 = (lane & 3) * 2;
    const int y  = y0 + warp;
    float* ob = out + (size_t)n * COUT * HWP + (size_t)y * WW;
    #pragma unroll
    for (int nt = 0; nt < 4; nt++) {
        const int co0 = nt * 8 + c0;
        const float bv0 = bias[co0], bv1 = bias[co0 + 1];
        #pragma unroll
        for (int m = 0; m < 2; m++) {
            const int px = x0 + m * 16 + g;
            ob[(size_t)co0 * HWP + px]           = d[m][nt][0] + bv0;
            ob[(size_t)(co0 + 1) * HWP + px]     = d[m][nt][1] + bv1;
            ob[(size_t)co0 * HWP + px + 8]       = d[m][nt][2] + bv0;
            ob[(size_t)(co0 + 1) * HWP + px + 8] = d[m][nt][3] + bv1;
        }
    }
}

// ---------------------------------------------------------------------------
extern "C" void kernel_launch(void* const* d_in, const int* in_sizes, int n_in,
                              void* d_out, int out_size) {
    const float* x    = (const float*)d_in[0];   // [16, 32, 192, 192]
    const float* wp   = (const float*)d_in[1];   // [32, 32, 3]
    const float* bias = (const float*)d_in[2];   // [32]
    float* out = (float*)d_out;                  // [16, 32, 192, 192]

    gk_compute<<<COUT, CIN>>>(wp);
    nchw_to_nhwc_h<<<dim3(WW / 32, HH, NB), dim3(32, 8)>>>(x);
    conv_mma<<<dim3(WW / 32, HH / 8, NB), 256>>>(bias, out);  // 2304 blocks
}

// round 12
// speedup vs baseline: 10.0469x; 1.1072x over previous
#include <cuda_runtime.h>
#include <cuda_fp16.h>
#include <cstdint>

typedef unsigned long long u64;

#define CIN   32
#define COUT  32
#define HH    192
#define WW    192
#define NB    16
#define HWP   (HH * WW)          // 36864
#define NPIX  (NB * HWP)
#define NTAP  81

// NHWC fp16 copy of input: [n][y][x][ci], 64B per pixel
__device__ __align__(16) __half g_xh[(size_t)NPIX * CIN];
// B fragments in mma register layout: [tap][kchunk 2][ntile 4][lane 32] u64 {b0,b1}
__device__ __align__(16) u64 g_wf[NTAP * 2 * 4 * 32];

// ---------------------------------------------------------------------------
// Prep 1: Gaussian kernels -> B fragments (one thread per (co, ci))
// ---------------------------------------------------------------------------
__global__ void gk_compute(const float* __restrict__ wp) {
    int co = blockIdx.x;
    int ci = threadIdx.x;
    const float* p = wp + (co * CIN + ci) * 3;
    float sx = p[0], sy = p[1], th = p[2];
    float rad = th * 0.017453292519943295f;   // th / 180 * pi (matches reference)
    float c = cosf(rad), s = sinf(rad);
    float sx2 = sx * sx, sy2 = sy * sy;
    float a = c * c * sx2 + s * s * sy2;
    float b = c * s * (sx2 - sy2);
    float d = s * s * sx2 + c * c * sy2;
    float det = a * d - b * b;
    float ia = d / det, ib = -b / det, idd = a / det;

    float ker[NTAP];
    float sum = 0.f;
    #pragma unroll
    for (int ky = 0; ky < 9; ky++) {
        float yy = (float)(ky - 4);
        #pragma unroll
        for (int kx = 0; kx < 9; kx++) {
            float xx = (float)(kx - 4);
            float q = ia * xx * xx + 2.0f * ib * xx * yy + idd * yy * yy;
            float v = expf(-0.5f * q);
            ker[ky * 9 + kx] = v;
            sum += v;
        }
    }
    float inv = 1.0f / sum;

    // B[k=ci][n=co]: fragment slot for (co, ci)
    int k     = ci >> 4;            // kchunk
    int kk    = ci & 15;            // row within 16
    int lane4 = (kk & 7) >> 1;      // threadID_in_group
    int sel   = ((kk >> 3) << 1) | (kk & 1);   // which half within {b0,b1}
    size_t idx = (((size_t)0 * 2 + k) * 4 + (co >> 3)) * 32 + ((co & 7) << 2) + lane4;
    __half* wf = (__half*)g_wf;
    #pragma unroll
    for (int t = 0; t < NTAP; t++) {
        wf[((size_t)t * 256 + idx) * 4 + sel] = __float2half_rn(ker[t] * inv);
    }
}

// ---------------------------------------------------------------------------
// Prep 2: NCHW fp32 -> NHWC fp16
// grid (192/32, 192, 16), block (32, 8)
// ---------------------------------------------------------------------------
__global__ void nchw_to_nhwc_h(const float* __restrict__ x) {
    __shared__ float t[32][33];
    const int x0 = blockIdx.x * 32;
    const int y  = blockIdx.y;
    const int n  = blockIdx.z;
    const float* src = x + (size_t)n * CIN * HWP + (size_t)y * WW + x0;
    #pragma unroll
    for (int ci = threadIdx.y; ci < 32; ci += 8)
        t[ci][threadIdx.x] = src[(size_t)ci * HWP + threadIdx.x];
    __syncthreads();
    const int tid = threadIdx.y * 32 + threadIdx.x;
    const int pix = tid >> 3;
    const int cg  = (tid & 7) * 4;
    __half2 h0 = __floats2half2_rn(t[cg + 0][pix], t[cg + 1][pix]);
    __half2 h1 = __floats2half2_rn(t[cg + 2][pix], t[cg + 3][pix]);
    uint2 v;
    v.x = *(uint32_t*)&h0;
    v.y = *(uint32_t*)&h1;
    *(uint2*)(g_xh + ((size_t)n * HWP + (size_t)y * WW + x0 + pix) * 32 + cg) = v;
}

// ---------------------------------------------------------------------------
// helpers
// ---------------------------------------------------------------------------
__device__ __forceinline__ uint32_t smem_u32(const void* p) {
    uint32_t a;
    asm("{ .reg .u64 t; cvta.to.shared.u64 t, %1; cvt.u32.u64 %0, t; }"
        : "=r"(a) : "l"(p));
    return a;
}
__device__ __forceinline__ void cpa16(uint32_t dst, const void* src, int szbytes) {
    asm volatile("cp.async.ca.shared.global [%0], [%1], 16, %2;"
                 :: "r"(dst), "l"(src), "r"(szbytes) : "memory");
}
__device__ __forceinline__ void mma16816(float* d,
                                         uint32_t a0, uint32_t a1, uint32_t a2, uint32_t a3,
                                         uint32_t b0, uint32_t b1) {
    asm volatile(
        "mma.sync.aligned.m16n8k16.row.col.f32.f16.f16.f32 "
        "{%0,%1,%2,%3},{%4,%5,%6,%7},{%8,%9},{%0,%1,%2,%3};"
        : "+f"(d[0]), "+f"(d[1]), "+f"(d[2]), "+f"(d[3])
        : "r"(a0), "r"(a1), "r"(a2), "r"(a3), "r"(b0), "r"(b1));
}
__device__ __forceinline__ void ldmat4(uint32_t* r, uint32_t addr) {
    asm volatile("ldmatrix.sync.aligned.m8n8.x4.shared.b16 {%0,%1,%2,%3}, [%4];"
                 : "=r"(r[0]), "=r"(r[1]), "=r"(r[2]), "=r"(r[3]) : "r"(addr));
}

// smem strip geometry: 16 rows x 72 pixels x 64B, 16B-segment swizzled
#define SPXB   64                  // bytes per pixel
#define SPX    72                  // pixels per strip row
#define SROWB  (SPX * SPXB)        // 4608 B per row
#define SSIZE  (16 * SROWB)        // 73728 B
#define NCH    (SSIZE / 16)        // 4608 16B chunks
__device__ __forceinline__ uint32_t sw_off(int p, int seg) {
    return (uint32_t)(p * 64 + ((seg ^ ((p >> 1) & 3)) << 4));
}

// ---------------------------------------------------------------------------
// Main: implicit conv. Block = 8 warps, covers 8 rows x 64 pixels.
// Warp w = row y0+w, 64 pixels (4 m16 tiles), D[64 x 32co] in registers.
// Input strip staged in smem once; A fragments via swizzled ldmatrix.x4.
// ---------------------------------------------------------------------------
__global__ __launch_bounds__(256, 2)
void conv_mma(const float* __restrict__ bias, float* __restrict__ out) {
    extern __shared__ __align__(16) char smem[];

    const int tid  = threadIdx.x;
    const int warp = tid >> 5;
    const int lane = tid & 31;
    const int x0 = blockIdx.x * 64;
    const int y0 = blockIdx.y * 8;
    const int n  = blockIdx.z;

    const uint32_t sb = smem_u32(smem);

    // ---- stage 16 rows x 72 px (zfill OOB): 4608 x 16B chunks, 18/thread ----
    {
        const __half* xb = g_xh + (size_t)n * HWP * 32;
        #pragma unroll
        for (int k = 0; k < 18; k++) {
            int i   = tid + k * 256;
            int row = i / 288;
            int rem = i - row * 288;
            int p   = rem >> 2;
            int seg = rem & 3;
            int gy  = y0 - 4 + row;
            int gx  = x0 - 4 + p;
            bool ok = ((unsigned)gy < HH) && ((unsigned)gx < WW);
            const __half* src = ok ? xb + ((size_t)gy * WW + gx) * 32 + seg * 8 : (const __half*)g_xh;
            cpa16(sb + row * SROWB + sw_off(p, seg), src, ok ? 16 : 0);
        }
        asm volatile("cp.async.commit_group;" ::: "memory");
        asm volatile("cp.async.wait_group 0;" ::: "memory");
        __syncthreads();
    }

    // ldmatrix lane geometry (verified R11): pixel offset pl, segment half sh
    const int pl = (lane & 7) + ((lane >> 3) & 1) * 8;
    const int sh = lane >> 4;

    float d[4][4][4] = {};   // [mtile][ntile][acc]

    #pragma unroll 1
    for (int dy = 0; dy < 9; dy++) {
        const uint32_t rowb = sb + (warp + dy) * SROWB;
        #pragma unroll 1
        for (int dx = 0; dx < 9; dx++) {
            // B fragments for this tap (L1-broadcast LDG.64 x8)
            const int tap = dy * 9 + dx;
            const uint2* wf = (const uint2*)g_wf + tap * 256 + lane;
            uint2 B0[4], B1[4];
            #pragma unroll
            for (int nt = 0; nt < 4; nt++) {
                B0[nt] = wf[nt * 32];          // kchunk 0
                B1[nt] = wf[128 + nt * 32];    // kchunk 1
            }

            #pragma unroll
            for (int m = 0; m < 4; m++) {
                const int p = dx + m * 16 + pl;
                uint32_t A0[4], A1[4];
                ldmat4(A0, rowb + sw_off(p, sh));        // kchunk 0
                ldmat4(A1, rowb + sw_off(p, 2 + sh));    // kchunk 1
                #pragma unroll
                for (int nt = 0; nt < 4; nt++) {
                    mma16816(d[m][nt], A0[0], A0[1], A0[2], A0[3], B0[nt].x, B0[nt].y);
                    mma16816(d[m][nt], A1[0], A1[1], A1[2], A1[3], B1[nt].x, B1[nt].y);
                }
            }
        }
    }

    // ---- epilogue: D rows = pixels, cols = co ----
    const int g  = lane >> 2;
    const int c0 = (lane & 3) * 2;
    const int y  = y0 + warp;
    float* ob = out + (size_t)n * COUT * HWP + (size_t)y * WW;
    #pragma unroll
    for (int nt = 0; nt < 4; nt++) {
        const int co0 = nt * 8 + c0;
        const float bv0 = bias[co0], bv1 = bias[co0 + 1];
        #pragma unroll
        for (int m = 0; m < 4; m++) {
            const int px = x0 + m * 16 + g;
            ob[(size_t)co0 * HWP + px]           = d[m][nt][0] + bv0;
            ob[(size_t)(co0 + 1) * HWP + px]     = d[m][nt][1] + bv1;
            ob[(size_t)co0 * HWP + px + 8]       = d[m][nt][2] + bv0;
            ob[(size_t)(co0 + 1) * HWP + px + 8] = d[m][nt][3] + bv1;
        }
    }
}

// ---------------------------------------------------------------------------
extern "C" void kernel_launch(void* const* d_in, const int* in_sizes, int n_in,
                              void* d_out, int out_size) {
    const float* x    = (const float*)d_in[0];   // [16, 32, 192, 192]
    const float* wp   = (const float*)d_in[1];   // [32, 32, 3]
    const float* bias = (const float*)d_in[2];   // [32]
    float* out = (float*)d_out;                  // [16, 32, 192, 192]

    cudaFuncSetAttribute(conv_mma, cudaFuncAttributeMaxDynamicSharedMemorySize, SSIZE);

    gk_compute<<<COUT, CIN>>>(wp);
    nchw_to_nhwc_h<<<dim3(WW / 32, HH, NB), dim3(32, 8)>>>(x);
    conv_mma<<<dim3(WW / 64, HH / 8, NB), 256, SSIZE>>>(bias, out);  // 1152 blocks
}

// round 14
// speedup vs baseline: 10.4920x; 1.0443x over previous
#include <cuda_runtime.h>
#include <cuda_fp16.h>
#include <cstdint>

typedef unsigned long long u64;

#define CIN   32
#define COUT  32
#define HH    192
#define WW    192
#define NB    16
#define HWP   (HH * WW)          // 36864
#define NPIX  (NB * HWP)
#define NTAP  81

// NHWC fp16 copy of input: [n][y][x][ci], 64B per pixel
__device__ __align__(16) __half g_xh[(size_t)NPIX * CIN];
// B fragments in mma register layout: [tap][kchunk 2][ntile 4][lane 32] u64 {b0,b1}
__device__ __align__(16) u64 g_wf[NTAP * 2 * 4 * 32];

// ---------------------------------------------------------------------------
// Prep 1: Gaussian kernels -> B fragments (one thread per (co, ci))
// ---------------------------------------------------------------------------
__global__ void gk_compute(const float* __restrict__ wp) {
    int co = blockIdx.x;
    int ci = threadIdx.x;
    const float* p = wp + (co * CIN + ci) * 3;
    float sx = p[0], sy = p[1], th = p[2];
    float rad = th * 0.017453292519943295f;   // th / 180 * pi (matches reference)
    float c = cosf(rad), s = sinf(rad);
    float sx2 = sx * sx, sy2 = sy * sy;
    float a = c * c * sx2 + s * s * sy2;
    float b = c * s * (sx2 - sy2);
    float d = s * s * sx2 + c * c * sy2;
    float det = a * d - b * b;
    float ia = d / det, ib = -b / det, idd = a / det;

    float ker[NTAP];
    float sum = 0.f;
    #pragma unroll
    for (int ky = 0; ky < 9; ky++) {
        float yy = (float)(ky - 4);
        #pragma unroll
        for (int kx = 0; kx < 9; kx++) {
            float xx = (float)(kx - 4);
            float q = ia * xx * xx + 2.0f * ib * xx * yy + idd * yy * yy;
            float v = expf(-0.5f * q);
            ker[ky * 9 + kx] = v;
            sum += v;
        }
    }
    float inv = 1.0f / sum;

    // B[k=ci][n=co]: fragment slot for (co, ci)
    int k     = ci >> 4;            // kchunk
    int kk    = ci & 15;            // row within 16
    int lane4 = (kk & 7) >> 1;      // threadID_in_group
    int sel   = ((kk >> 3) << 1) | (kk & 1);   // which half within {b0,b1}
    size_t idx = (((size_t)0 * 2 + k) * 4 + (co >> 3)) * 32 + ((co & 7) << 2) + lane4;
    __half* wf = (__half*)g_wf;
    #pragma unroll
    for (int t = 0; t < NTAP; t++) {
        wf[((size_t)t * 256 + idx) * 4 + sel] = __float2half_rn(ker[t] * inv);
    }
}

// ---------------------------------------------------------------------------
// Prep 2: NCHW fp32 -> NHWC fp16
// grid (192/32, 192, 16), block (32, 8)
// ---------------------------------------------------------------------------
__global__ void nchw_to_nhwc_h(const float* __restrict__ x) {
    __shared__ float t[32][33];
    const int x0 = blockIdx.x * 32;
    const int y  = blockIdx.y;
    const int n  = blockIdx.z;
    const float* src = x + (size_t)n * CIN * HWP + (size_t)y * WW + x0;
    #pragma unroll
    for (int ci = threadIdx.y; ci < 32; ci += 8)
        t[ci][threadIdx.x] = src[(size_t)ci * HWP + threadIdx.x];
    __syncthreads();
    const int tid = threadIdx.y * 32 + threadIdx.x;
    const int pix = tid >> 3;
    const int cg  = (tid & 7) * 4;
    __half2 h0 = __floats2half2_rn(t[cg + 0][pix], t[cg + 1][pix]);
    __half2 h1 = __floats2half2_rn(t[cg + 2][pix], t[cg + 3][pix]);
    uint2 v;
    v.x = *(uint32_t*)&h0;
    v.y = *(uint32_t*)&h1;
    *(uint2*)(g_xh + ((size_t)n * HWP + (size_t)y * WW + x0 + pix) * 32 + cg) = v;
}

// ---------------------------------------------------------------------------
// helpers
// ---------------------------------------------------------------------------
__device__ __forceinline__ uint32_t smem_u32(const void* p) {
    uint32_t a;
    asm("{ .reg .u64 t; cvta.to.shared.u64 t, %1; cvt.u32.u64 %0, t; }"
        : "=r"(a) : "l"(p));
    return a;
}
__device__ __forceinline__ void cpa16(uint32_t dst, const void* src, int szbytes) {
    asm volatile("cp.async.ca.shared.global [%0], [%1], 16, %2;"
                 :: "r"(dst), "l"(src), "r"(szbytes) : "memory");
}
__device__ __forceinline__ void mma16816(float* d,
                                         uint32_t a0, uint32_t a1, uint32_t a2, uint32_t a3,
                                         uint32_t b0, uint32_t b1) {
    asm volatile(
        "mma.sync.aligned.m16n8k16.row.col.f32.f16.f16.f32 "
        "{%0,%1,%2,%3},{%4,%5,%6,%7},{%8,%9},{%0,%1,%2,%3};"
        : "+f"(d[0]), "+f"(d[1]), "+f"(d[2]), "+f"(d[3])
        : "r"(a0), "r"(a1), "r"(a2), "r"(a3), "r"(b0), "r"(b1));
}
__device__ __forceinline__ void ldmat4(uint32_t* r, uint32_t addr) {
    asm volatile("ldmatrix.sync.aligned.m8n8.x4.shared.b16 {%0,%1,%2,%3}, [%4];"
                 : "=r"(r[0]), "=r"(r[1]), "=r"(r[2]), "=r"(r[3]) : "r"(addr));
}

// smem strip geometry: 16 rows x 72 pixels x 64B, 16B-segment swizzled
#define SPXB   64                  // bytes per pixel
#define SPX    72                  // pixels per strip row
#define SROWB  (SPX * SPXB)        // 4608 B per row
#define SSIZE  (16 * SROWB)        // 73728 B
__device__ __forceinline__ uint32_t sw_off(int p, int seg) {
    return (uint32_t)(p * 64 + ((seg ^ ((p >> 1) & 3)) << 4));
}

// ---------------------------------------------------------------------------
// Main: implicit conv. Block = 8 warps, covers 8 rows x 64 pixels.
// Warp w = row y0+w, 64 pixels (4 m16 tiles), D[64 x 32co] in registers.
// Input strip staged in smem once; A fragments via swizzled ldmatrix.x4.
// dx loop fully unrolled: lets ptxas pipeline next-tap LDSM/LDG under HMMAs.
// ---------------------------------------------------------------------------
__global__ __launch_bounds__(256, 2)
void conv_mma(const float* __restrict__ bias, float* __restrict__ out) {
    extern __shared__ __align__(16) char smem[];

    const int tid  = threadIdx.x;
    const int warp = tid >> 5;
    const int lane = tid & 31;
    const int x0 = blockIdx.x * 64;
    const int y0 = blockIdx.y * 8;
    const int n  = blockIdx.z;

    const uint32_t sb = smem_u32(smem);

    // ---- stage 16 rows x 72 px (zfill OOB): 4608 x 16B chunks, 18/thread ----
    {
        const __half* xb = g_xh + (size_t)n * HWP * 32;
        #pragma unroll
        for (int k = 0; k < 18; k++) {
            int i   = tid + k * 256;
            int row = i / 288;
            int rem = i - row * 288;
            int p   = rem >> 2;
            int seg = rem & 3;
            int gy  = y0 - 4 + row;
            int gx  = x0 - 4 + p;
            bool ok = ((unsigned)gy < HH) && ((unsigned)gx < WW);
            const __half* src = ok ? xb + ((size_t)gy * WW + gx) * 32 + seg * 8 : (const __half*)g_xh;
            cpa16(sb + row * SROWB + sw_off(p, seg), src, ok ? 16 : 0);
        }
        asm volatile("cp.async.commit_group;" ::: "memory");
        asm volatile("cp.async.wait_group 0;" ::: "memory");
        __syncthreads();
    }

    // ldmatrix lane geometry (verified R11): pixel offset pl, segment half sh
    const int pl = (lane & 7) + ((lane >> 3) & 1) * 8;
    const int sh = lane >> 4;

    float d[4][4][4] = {};   // [mtile][ntile][acc]

    #pragma unroll 1
    for (int dy = 0; dy < 9; dy++) {
        const uint32_t rowb = sb + (warp + dy) * SROWB;
        #pragma unroll
        for (int dx = 0; dx < 9; dx++) {
            // B fragments for this tap (L1-broadcast LDG.64 x8)
            const int tap = dy * 9 + dx;
            const uint2* wf = (const uint2*)g_wf + tap * 256 + lane;
            uint2 B0[4], B1[4];
            #pragma unroll
            for (int nt = 0; nt < 4; nt++) {
                B0[nt] = wf[nt * 32];          // kchunk 0
                B1[nt] = wf[128 + nt * 32];    // kchunk 1
            }

            #pragma unroll
            for (int m = 0; m < 4; m++) {
                const int p = dx + m * 16 + pl;
                uint32_t A0[4], A1[4];
                ldmat4(A0, rowb + sw_off(p, sh));        // kchunk 0
                ldmat4(A1, rowb + sw_off(p, 2 + sh));    // kchunk 1
                #pragma unroll
                for (int nt = 0; nt < 4; nt++) {
                    mma16816(d[m][nt], A0[0], A0[1], A0[2], A0[3], B0[nt].x, B0[nt].y);
                    mma16816(d[m][nt], A1[0], A1[1], A1[2], A1[3], B1[nt].x, B1[nt].y);
                }
            }
        }
    }

    // ---- epilogue: D rows = pixels, cols = co ----
    const int g  = lane >> 2;
    const int c0 = (lane & 3) * 2;
    const int y  = y0 + warp;
    float* ob = out + (size_t)n * COUT * HWP + (size_t)y * WW;
    #pragma unroll
    for (int nt = 0; nt < 4; nt++) {
        const int co0 = nt * 8 + c0;
        const float bv0 = bias[co0], bv1 = bias[co0 + 1];
        #pragma unroll
        for (int m = 0; m < 4; m++) {
            const int px = x0 + m * 16 + g;
            ob[(size_t)co0 * HWP + px]           = d[m][nt][0] + bv0;
            ob[(size_t)(co0 + 1) * HWP + px]     = d[m][nt][1] + bv1;
            ob[(size_t)co0 * HWP + px + 8]       = d[m][nt][2] + bv0;
            ob[(size_t)(co0 + 1) * HWP + px + 8] = d[m][nt][3] + bv1;
        }
    }
}

// ---------------------------------------------------------------------------
extern "C" void kernel_launch(void* const* d_in, const int* in_sizes, int n_in,
                              void* d_out, int out_size) {
    const float* x    = (const float*)d_in[0];   // [16, 32, 192, 192]
    const float* wp   = (const float*)d_in[1];   // [32, 32, 3]
    const float* bias = (const float*)d_in[2];   // [32]
    float* out = (float*)d_out;                  // [16, 32, 192, 192]

    cudaFuncSetAttribute(conv_mma, cudaFuncAttributeMaxDynamicSharedMemorySize, SSIZE);

    gk_compute<<<COUT, CIN>>>(wp);
    nchw_to_nhwc_h<<<dim3(WW / 32, HH, NB), dim3(32, 8)>>>(x);
    conv_mma<<<dim3(WW / 64, HH / 8, NB), 256, SSIZE>>>(bias, out);  // 1152 blocks
}

// round 15
// speedup vs baseline: 10.5298x; 1.0036x over previous
#include <cuda_runtime.h>
#include <cuda_fp16.h>
#include <cstdint>

typedef unsigned long long u64;

#define CIN   32
#define COUT  32
#define HH    192
#define WW    192
#define NB    16
#define HWP   (HH * WW)          // 36864
#define NPIX  (NB * HWP)
#define NTAP  81

// NHWC fp16 copy of input: [n][y][x][ci], 64B per pixel
__device__ __align__(16) __half g_xh[(size_t)NPIX * CIN];
// B fragments, packed per ntile: [tap][ntile 4][lane 32] uint4 {B0lo,B0hi,B1lo,B1hi}
__device__ __align__(16) uint4 g_wf[NTAP * 4 * 32];

// ---------------------------------------------------------------------------
// Prep 1: Gaussian kernels -> B fragments (one thread per (co, ci))
// ---------------------------------------------------------------------------
__global__ void gk_compute(const float* __restrict__ wp) {
    int co = blockIdx.x;
    int ci = threadIdx.x;
    const float* p = wp + (co * CIN + ci) * 3;
    float sx = p[0], sy = p[1], th = p[2];
    float rad = th * 0.017453292519943295f;   // th / 180 * pi (matches reference)
    float c = cosf(rad), s = sinf(rad);
    float sx2 = sx * sx, sy2 = sy * sy;
    float a = c * c * sx2 + s * s * sy2;
    float b = c * s * (sx2 - sy2);
    float d = s * s * sx2 + c * c * sy2;
    float det = a * d - b * b;
    float ia = d / det, ib = -b / det, idd = a / det;

    float ker[NTAP];
    float sum = 0.f;
    #pragma unroll
    for (int ky = 0; ky < 9; ky++) {
        float yy = (float)(ky - 4);
        #pragma unroll
        for (int kx = 0; kx < 9; kx++) {
            float xx = (float)(kx - 4);
            float q = ia * xx * xx + 2.0f * ib * xx * yy + idd * yy * yy;
            float v = expf(-0.5f * q);
            ker[ky * 9 + kx] = v;
            sum += v;
        }
    }
    float inv = 1.0f / sum;

    // B[k=ci][n=co] fragment slot: uint4 = {kchunk0 (4 halves), kchunk1 (4 halves)}
    int k     = ci >> 4;            // kchunk
    int kk    = ci & 15;            // row within 16
    int lane4 = (kk & 7) >> 1;      // threadID_in_group
    int sel   = ((kk >> 3) << 1) | (kk & 1);   // half index within kchunk's 4
    int nt    = co >> 3;
    int lane  = ((co & 7) << 2) + lane4;
    size_t hidx = ((size_t)nt * 32 + lane) * 8 + k * 4 + sel;   // half index within tap slab
    __half* wf = (__half*)g_wf;
    #pragma unroll
    for (int t = 0; t < NTAP; t++) {
        wf[(size_t)t * 1024 + hidx] = __float2half_rn(ker[t] * inv);
    }
}

// ---------------------------------------------------------------------------
// Prep 2: NCHW fp32 -> NHWC fp16
// grid (192/32, 192, 16), block (32, 8)
// ---------------------------------------------------------------------------
__global__ void nchw_to_nhwc_h(const float* __restrict__ x) {
    __shared__ float t[32][33];
    const int x0 = blockIdx.x * 32;
    const int y  = blockIdx.y;
    const int n  = blockIdx.z;
    const float* src = x + (size_t)n * CIN * HWP + (size_t)y * WW + x0;
    #pragma unroll
    for (int ci = threadIdx.y; ci < 32; ci += 8)
        t[ci][threadIdx.x] = src[(size_t)ci * HWP + threadIdx.x];
    __syncthreads();
    const int tid = threadIdx.y * 32 + threadIdx.x;
    const int pix = tid >> 3;
    const int cg  = (tid & 7) * 4;
    __half2 h0 = __floats2half2_rn(t[cg + 0][pix], t[cg + 1][pix]);
    __half2 h1 = __floats2half2_rn(t[cg + 2][pix], t[cg + 3][pix]);
    uint2 v;
    v.x = *(uint32_t*)&h0;
    v.y = *(uint32_t*)&h1;
    *(uint2*)(g_xh + ((size_t)n * HWP + (size_t)y * WW + x0 + pix) * 32 + cg) = v;
}

// ---------------------------------------------------------------------------
// helpers
// ---------------------------------------------------------------------------
__device__ __forceinline__ uint32_t smem_u32(const void* p) {
    uint32_t a;
    asm("{ .reg .u64 t; cvta.to.shared.u64 t, %1; cvt.u32.u64 %0, t; }"
        : "=r"(a) : "l"(p));
    return a;
}
__device__ __forceinline__ void cpa16(uint32_t dst, const void* src, int szbytes) {
    asm volatile("cp.async.ca.shared.global [%0], [%1], 16, %2;"
                 :: "r"(dst), "l"(src), "r"(szbytes) : "memory");
}
__device__ __forceinline__ void mma16816(float* d,
                                         uint32_t a0, uint32_t a1, uint32_t a2, uint32_t a3,
                                         uint32_t b0, uint32_t b1) {
    asm volatile(
        "mma.sync.aligned.m16n8k16.row.col.f32.f16.f16.f32 "
        "{%0,%1,%2,%3},{%4,%5,%6,%7},{%8,%9},{%0,%1,%2,%3};"
        : "+f"(d[0]), "+f"(d[1]), "+f"(d[2]), "+f"(d[3])
        : "r"(a0), "r"(a1), "r"(a2), "r"(a3), "r"(b0), "r"(b1));
}
__device__ __forceinline__ void ldmat4(uint32_t* r, uint32_t addr) {
    asm volatile("ldmatrix.sync.aligned.m8n8.x4.shared.b16 {%0,%1,%2,%3}, [%4];"
                 : "=r"(r[0]), "=r"(r[1]), "=r"(r[2]), "=r"(r[3]) : "r"(addr));
}

// smem strip geometry: 16 rows x 72 pixels x 64B, 16B-segment swizzled
#define SPXB   64                  // bytes per pixel
#define SPX    72                  // pixels per strip row
#define SROWB  (SPX * SPXB)        // 4608 B per row
#define SSIZE  (16 * SROWB)        // 73728 B
__device__ __forceinline__ uint32_t sw_off(int p, int seg) {
    return (uint32_t)(p * 64 + ((seg ^ ((p >> 1) & 3)) << 4));
}

// ---------------------------------------------------------------------------
// Main: implicit conv. Block = 8 warps, covers 8 rows x 64 pixels.
// Warp w = row y0+w, 64 pixels (4 m16 tiles), D[64 x 32co] in registers.
// Input strip staged in smem once; A via swizzled ldmatrix.x4; B via LDG.128.
// ---------------------------------------------------------------------------
__global__ __launch_bounds__(256, 2)
void conv_mma(const float* __restrict__ bias, float* __restrict__ out) {
    extern __shared__ __align__(16) char smem[];

    const int tid  = threadIdx.x;
    const int warp = tid >> 5;
    const int lane = tid & 31;
    const int x0 = blockIdx.x * 64;
    const int y0 = blockIdx.y * 8;
    const int n  = blockIdx.z;

    const uint32_t sb = smem_u32(smem);

    // ---- stage 16 rows x 72 px (zfill OOB): 4608 x 16B chunks, 18/thread ----
    {
        const __half* xb = g_xh + (size_t)n * HWP * 32;
        #pragma unroll
        for (int k = 0; k < 18; k++) {
            int i   = tid + k * 256;
            int row = i / 288;
            int rem = i - row * 288;
            int p   = rem >> 2;
            int seg = rem & 3;
            int gy  = y0 - 4 + row;
            int gx  = x0 - 4 + p;
            bool ok = ((unsigned)gy < HH) && ((unsigned)gx < WW);
            const __half* src = ok ? xb + ((size_t)gy * WW + gx) * 32 + seg * 8 : (const __half*)g_xh;
            cpa16(sb + row * SROWB + sw_off(p, seg), src, ok ? 16 : 0);
        }
        asm volatile("cp.async.commit_group;" ::: "memory");
        asm volatile("cp.async.wait_group 0;" ::: "memory");
        __syncthreads();
    }

    // ldmatrix lane geometry (verified R11): pixel offset pl, segment half sh
    const int pl = (lane & 7) + ((lane >> 3) & 1) * 8;
    const int sh = lane >> 4;

    float d[4][4][4] = {};   // [mtile][ntile][acc]

    #pragma unroll 1
    for (int dy = 0; dy < 9; dy++) {
        const uint32_t rowb = sb + (warp + dy) * SROWB;
        #pragma unroll
        for (int dx = 0; dx < 9; dx++) {
            // B fragments for this tap: 4x LDG.128 (both kchunks packed per ntile)
            const int tap = dy * 9 + dx;
            const uint4* wf = g_wf + tap * 128 + lane;
            uint4 B[4];
            #pragma unroll
            for (int nt = 0; nt < 4; nt++) B[nt] = wf[nt * 32];

            #pragma unroll
            for (int m = 0; m < 4; m++) {
                const int p = dx + m * 16 + pl;
                uint32_t A0[4], A1[4];
                ldmat4(A0, rowb + sw_off(p, sh));        // kchunk 0
                ldmat4(A1, rowb + sw_off(p, 2 + sh));    // kchunk 1
                #pragma unroll
                for (int nt = 0; nt < 4; nt++) {
                    mma16816(d[m][nt], A0[0], A0[1], A0[2], A0[3], B[nt].x, B[nt].y);
                    mma16816(d[m][nt], A1[0], A1[1], A1[2], A1[3], B[nt].z, B[nt].w);
                }
            }
        }
    }

    // ---- epilogue: D rows = pixels, cols = co ----
    const int g  = lane >> 2;
    const int c0 = (lane & 3) * 2;
    const int y  = y0 + warp;
    float* ob = out + (size_t)n * COUT * HWP + (size_t)y * WW;
    #pragma unroll
    for (int nt = 0; nt < 4; nt++) {
        const int co0 = nt * 8 + c0;
        const float bv0 = bias[co0], bv1 = bias[co0 + 1];
        #pragma unroll
        for (int m = 0; m < 4; m++) {
            const int px = x0 + m * 16 + g;
            ob[(size_t)co0 * HWP + px]           = d[m][nt][0] + bv0;
            ob[(size_t)(co0 + 1) * HWP + px]     = d[m][nt][1] + bv1;
            ob[(size_t)co0 * HWP + px + 8]       = d[m][nt][2] + bv0;
            ob[(size_t)(co0 + 1) * HWP + px + 8] = d[m][nt][3] + bv1;
        }
    }
}

// ---------------------------------------------------------------------------
extern "C" void kernel_launch(void* const* d_in, const int* in_sizes, int n_in,
                              void* d_out, int out_size) {
    const float* x    = (const float*)d_in[0];   // [16, 32, 192, 192]
    const float* wp   = (const float*)d_in[1];   // [32, 32, 3]
    const float* bias = (const float*)d_in[2];   // [32]
    float* out = (float*)d_out;                  // [16, 32, 192, 192]

    cudaFuncSetAttribute(conv_mma, cudaFuncAttributeMaxDynamicSharedMemorySize, SSIZE);

    gk_compute<<<COUT, CIN>>>(wp);
    nchw_to_nhwc_h<<<dim3(WW / 32, HH, NB), dim3(32, 8)>>>(x);
    conv_mma<<<dim3(WW / 64, HH / 8, NB), 256, SSIZE>>>(bias, out);  // 1152 blocks
}